// round 14
// baseline (speedup 1.0000x reference)
#include <cuda_runtime.h>
#include <cuda_bf16.h>
#include <cstdint>

#define TOK_TOTAL 32768
#define NCTA 512                  // 64 tokens per CTA, 4 warps x 16 tokens

extern __shared__ __align__(128) uint8_t smbuf[];

// fp16 B panels, v4-packed (layout unchanged)
__device__ __align__(16) uint8_t g_BpkH[65 * 8192];
__device__ __align__(16) uint8_t g_W3pkH[8192];
__device__ __align__(16) uint8_t g_W11pk[32768];
__device__ __align__(16) uint8_t g_W21pk[32768];
__device__ __align__(16) uint8_t g_W12pk[16384];
// per-tile intermediates produced by prep_kernel
__device__ __align__(16) uint32_t g_w12f[2048 * 512];   // f16x2 frags, [tile][l][16]
__device__ __align__(16) float    g_w21[TOK_TOTAL * 64];

// ---------------------------------------------------------------------------
__device__ __forceinline__ void split_pair(float v0, float v1, uint32_t& h, uint32_t& l) {
    asm("cvt.rn.bf16x2.f32 %0, %1, %2;" : "=r"(h) : "f"(v1), "f"(v0));
    float h0 = __uint_as_float(h << 16);
    float h1 = __uint_as_float(h & 0xffff0000u);
    asm("cvt.rn.bf16x2.f32 %0, %1, %2;" : "=r"(l) : "f"(v1 - h1), "f"(v0 - h0));
}
__device__ __forceinline__ uint32_t f16x2(float v0, float v1) {
    uint32_t r;
    asm("cvt.rn.f16x2.f32 %0, %1, %2;" : "=r"(r) : "f"(v1), "f"(v0));
    return r;
}
__device__ __forceinline__ uint32_t hmul2(uint32_t a, uint32_t b) {
    uint32_t r;
    asm("mul.rn.f16x2 %0, %1, %2;" : "=r"(r) : "r"(a), "r"(b));
    return r;
}

#define MMA_BF16(Cq, A, b0, b1)                                              \
    asm volatile("mma.sync.aligned.m16n8k16.row.col.f32.bf16.bf16.f32 "      \
                 "{%0,%1,%2,%3}, {%4,%5,%6,%7}, {%8,%9}, {%0,%1,%2,%3};"     \
                 : "+f"((Cq)[0]), "+f"((Cq)[1]), "+f"((Cq)[2]), "+f"((Cq)[3])\
                 : "r"((A)[0]), "r"((A)[1]), "r"((A)[2]), "r"((A)[3]),       \
                   "r"(b0), "r"(b1))

#define MMA_F16(Cq, A, b0, b1)                                               \
    asm volatile("mma.sync.aligned.m16n8k16.row.col.f32.f16.f16.f32 "        \
                 "{%0,%1,%2,%3}, {%4,%5,%6,%7}, {%8,%9}, {%0,%1,%2,%3};"     \
                 : "+f"((Cq)[0]), "+f"((Cq)[1]), "+f"((Cq)[2]), "+f"((Cq)[3])\
                 : "r"((A)[0]), "r"((A)[1]), "r"((A)[2]), "r"((A)[3]),       \
                   "r"(b0), "r"(b1))

// ---------------------------------------------------------------------------
// Convert (unchanged)
// ---------------------------------------------------------------------------
__device__ __forceinline__ void pack_frag_bf(const float* src, uint8_t* dst,
                                             int kc, int nt, int l, int loOff) {
    int q2 = (l & 3) * 2;
    int o  = nt * 8 + (l >> 2);
    int i0 = kc * 16 + q2;
    float v0 = src[(i0    ) * 64 + o];
    float v1 = src[(i0 + 1) * 64 + o];
    float v2 = src[(i0 + 8) * 64 + o];
    float v3 = src[(i0 + 9) * 64 + o];
    uint32_t h0, l0, h1, l1;
    split_pair(v0, v1, h0, l0);
    split_pair(v2, v3, h1, l1);
    uint8_t* d = dst + (kc * 8 + nt) * 256 + l * 8;
    *(uint32_t*)(d)             = h0;
    *(uint32_t*)(d + 4)         = h1;
    *(uint32_t*)(d + loOff)     = l0;
    *(uint32_t*)(d + loOff + 4) = l1;
}
__device__ __forceinline__ void pack_frag_h4(const float* src, uint8_t* dst,
                                             int kc, int np, int l) {
    int q2 = (l & 3) * 2;
    int i0 = kc * 16 + q2;
    uint32_t r[4];
    #pragma unroll
    for (int h = 0; h < 2; h++) {
        int o = (2 * np + h) * 8 + (l >> 2);
        r[h*2+0] = f16x2(src[(i0    ) * 64 + o], src[(i0 + 1) * 64 + o]);
        r[h*2+1] = f16x2(src[(i0 + 8) * 64 + o], src[(i0 + 9) * 64 + o]);
    }
    *(uint4*)(dst + (kc * 4 + np) * 512 + l * 16) = make_uint4(r[0], r[1], r[2], r[3]);
}

__global__ __launch_bounds__(256) void convert_kernel(
    const float* __restrict__ W22, const float* __restrict__ b22,
    const float* __restrict__ W3,  const float* __restrict__ W11,
    const float* __restrict__ W21, const float* __restrict__ W12)
{
    int gid = blockIdx.x * 256 + threadIdx.x;
    if (gid < 33280) {
        int j = gid >> 9;
        int r = gid & 511;
        const float* src = (j < 64) ? (W22 + j * 4096) : b22;
        pack_frag_h4(src, g_BpkH + j * 8192, r >> 7, (r >> 5) & 3, r & 31);
    } else if (gid < 33792) {
        int r = gid - 33280;
        pack_frag_h4(W3, g_W3pkH, r >> 7, (r >> 5) & 3, r & 31);
    } else if (gid < 35840) {
        int r = gid - 33792;
        pack_frag_bf(W11, g_W11pk, r >> 8, (r >> 5) & 7, r & 31, 16384);
    } else if (gid < 37888) {
        int r = gid - 35840;
        pack_frag_bf(W21, g_W21pk, r >> 8, (r >> 5) & 7, r & 31, 16384);
    } else if (gid < 38912) {
        int r = gid - 37888;
        pack_frag_bf(W12, g_W12pk, r >> 8, (r >> 5) & 7, r & 31, 8192);
    }
}

// ---------------------------------------------------------------------------
// Prep kernel: phase 1 only (register-heavy but small fraction of work).
// warp = 16-token tile: C1=relu(cat@W11+b11); w12f=f16pack(C1@W12+b12);
// w21=relu(cat@W21+b21) -> g_w21 rows.
// ---------------------------------------------------------------------------
__device__ __forceinline__ float2 catld(const float* __restrict__ img,
                                        const float* __restrict__ loc,
                                        int row, int c) {
    if (c < 64) return *(const float2*)&img[row * 64 + c];
    return *(const float2*)&loc[row * 64 + c - 64];
}

__global__ __launch_bounds__(128, 2) void prep_kernel(
    const float* __restrict__ img, const float* __restrict__ loc,
    const float* __restrict__ b11, const float* __restrict__ b21,
    const float* __restrict__ b12)
{
    const int tid  = threadIdx.x;
    const int l    = tid & 31;
    const int w    = tid >> 5;
    const int tile = blockIdx.x * 4 + w;
    const int g    = l >> 2;
    const int q2   = (l & 3) * 2;
    const int gra  = tile * 16 + g;
    const int grb  = gra + 8;

    float C1[8][4];
    #pragma unroll
    for (int nt = 0; nt < 8; nt++)
        #pragma unroll
        for (int k = 0; k < 4; k++) C1[nt][k] = 0.f;

    #pragma unroll
    for (int kc = 0; kc < 8; kc++) {
        const int i0 = kc * 16 + q2;
        float2 p0 = catld(img, loc, gra, i0);
        float2 p1 = catld(img, loc, grb, i0);
        float2 p2 = catld(img, loc, gra, i0 + 8);
        float2 p3 = catld(img, loc, grb, i0 + 8);
        uint32_t ah[4], al[4];
        split_pair(p0.x, p0.y, ah[0], al[0]);
        split_pair(p1.x, p1.y, ah[1], al[1]);
        split_pair(p2.x, p2.y, ah[2], al[2]);
        split_pair(p3.x, p3.y, ah[3], al[3]);
        #pragma unroll
        for (int nt = 0; nt < 8; nt++) {
            const uint8_t* p = g_W11pk + (kc * 8 + nt) * 256 + l * 8;
            uint2 bh = __ldg((const uint2*)p);
            uint2 bl = __ldg((const uint2*)(p + 16384));
            MMA_BF16(C1[nt], ah, bh.x, bh.y);
            MMA_BF16(C1[nt], ah, bl.x, bl.y);
            MMA_BF16(C1[nt], al, bh.x, bh.y);
        }
    }
    #pragma unroll
    for (int nt = 0; nt < 8; nt++) {
        int col = nt * 8 + q2;
        float u0 = __ldg(b11 + col), u1 = __ldg(b11 + col + 1);
        C1[nt][0] = fmaxf(C1[nt][0] + u0, 0.f);
        C1[nt][1] = fmaxf(C1[nt][1] + u1, 0.f);
        C1[nt][2] = fmaxf(C1[nt][2] + u0, 0.f);
        C1[nt][3] = fmaxf(C1[nt][3] + u1, 0.f);
    }

    // Wf = C1 @ W12 + b12 -> f16 pack -> g_w12f
    float Wf[8][4];
    #pragma unroll
    for (int nt = 0; nt < 8; nt++)
        #pragma unroll
        for (int k = 0; k < 4; k++) Wf[nt][k] = 0.f;

    #pragma unroll
    for (int kc = 0; kc < 4; kc++) {
        uint32_t ah[4], al[4];
        split_pair(C1[2*kc][0],   C1[2*kc][1],   ah[0], al[0]);
        split_pair(C1[2*kc][2],   C1[2*kc][3],   ah[1], al[1]);
        split_pair(C1[2*kc+1][0], C1[2*kc+1][1], ah[2], al[2]);
        split_pair(C1[2*kc+1][2], C1[2*kc+1][3], ah[3], al[3]);
        #pragma unroll
        for (int nt = 0; nt < 8; nt++) {
            const uint8_t* p = g_W12pk + (kc * 8 + nt) * 256 + l * 8;
            uint2 bh = __ldg((const uint2*)p);
            uint2 bl = __ldg((const uint2*)(p + 8192));
            MMA_BF16(Wf[nt], ah, bh.x, bh.y);
            MMA_BF16(Wf[nt], ah, bl.x, bl.y);
            MMA_BF16(Wf[nt], al, bh.x, bh.y);
        }
    }
    #pragma unroll
    for (int kc = 0; kc < 4; kc++) {
        int c0 = (2*kc) * 8 + q2, c1 = (2*kc+1) * 8 + q2;
        float e00 = __ldg(b12 + c0), e01 = __ldg(b12 + c0 + 1);
        float e10 = __ldg(b12 + c1), e11 = __ldg(b12 + c1 + 1);
        uint4 v;
        v.x = f16x2(Wf[2*kc][0] + e00,   Wf[2*kc][1] + e01);
        v.y = f16x2(Wf[2*kc][2] + e00,   Wf[2*kc][3] + e01);
        v.z = f16x2(Wf[2*kc+1][0] + e10, Wf[2*kc+1][1] + e11);
        v.w = f16x2(Wf[2*kc+1][2] + e10, Wf[2*kc+1][3] + e11);
        *(uint4*)&g_w12f[tile * 512 + l * 16 + kc * 4] = v;
    }

    // C2 = relu(cat @ W21 + b21) -> g_w21 rows (reuse C1 regs)
    #pragma unroll
    for (int nt = 0; nt < 8; nt++)
        #pragma unroll
        for (int k = 0; k < 4; k++) C1[nt][k] = 0.f;

    #pragma unroll
    for (int kc = 0; kc < 8; kc++) {
        const int i0 = kc * 16 + q2;
        float2 p0 = catld(img, loc, gra, i0);
        float2 p1 = catld(img, loc, grb, i0);
        float2 p2 = catld(img, loc, gra, i0 + 8);
        float2 p3 = catld(img, loc, grb, i0 + 8);
        uint32_t ah[4], al[4];
        split_pair(p0.x, p0.y, ah[0], al[0]);
        split_pair(p1.x, p1.y, ah[1], al[1]);
        split_pair(p2.x, p2.y, ah[2], al[2]);
        split_pair(p3.x, p3.y, ah[3], al[3]);
        #pragma unroll
        for (int nt = 0; nt < 8; nt++) {
            const uint8_t* p = g_W21pk + (kc * 8 + nt) * 256 + l * 8;
            uint2 bh = __ldg((const uint2*)p);
            uint2 bl = __ldg((const uint2*)(p + 16384));
            MMA_BF16(C1[nt], ah, bh.x, bh.y);
            MMA_BF16(C1[nt], ah, bl.x, bl.y);
            MMA_BF16(C1[nt], al, bh.x, bh.y);
        }
    }
    #pragma unroll
    for (int nt = 0; nt < 8; nt++) {
        int col = nt * 8 + q2;
        float v0 = __ldg(b21 + col), v1 = __ldg(b21 + col + 1);
        *(float2*)&g_w21[gra * 64 + col] =
            make_float2(fmaxf(C1[nt][0] + v0, 0.f), fmaxf(C1[nt][1] + v1, 0.f));
        *(float2*)&g_w21[grb * 64 + col] =
            make_float2(fmaxf(C1[nt][2] + v0, 0.f), fmaxf(C1[nt][3] + v1, 0.f));
    }
}

// ---------------------------------------------------------------------------
// Main kernel: slim (target <=128 regs, 4 CTAs/SM). 4 warps x 16 tokens.
// Dual j-stream interleaved loop (R13), zero block barriers.
// smem: per-warp w21s[64][17] f32 -> 4 x 4352 B = 17408 B.
// ---------------------------------------------------------------------------
#define S_SZ 17408u

__global__ __launch_bounds__(128, 4) void main_kernel(
    const float* __restrict__ lnG, const float* __restrict__ lnB,
    const float* __restrict__ b3,  float* __restrict__ out)
{
    const int tid  = threadIdx.x;
    const int l    = tid & 31;
    const int w    = tid >> 5;
    const int tile = blockIdx.x * 4 + w;
    const int g    = l >> 2;
    const int q2   = (l & 3) * 2;
    const int gra  = tile * 16 + g;
    const int grb  = gra + 8;

    float* w21s = (float*)smbuf + w * 1088;   // [64][17]

    // load packed w12 fragments
    uint32_t w12p[16];
    #pragma unroll
    for (int kc = 0; kc < 4; kc++) {
        uint4 v = __ldg((const uint4*)&g_w12f[tile * 512 + l * 16 + kc * 4]);
        w12p[kc*4+0] = v.x; w12p[kc*4+1] = v.y;
        w12p[kc*4+2] = v.z; w12p[kc*4+3] = v.w;
    }
    // stage this warp's w21 block transposed into smem
    {
        const float* wsrc = g_w21 + tile * 16 * 64;
        #pragma unroll
        for (int it = 0; it < 8; it++) {
            int idx   = it * 32 + l;          // 0..255
            int token = idx >> 4;
            int c4    = (idx & 15) * 4;
            float4 v  = __ldg((const float4*)(wsrc + token * 64 + c4));
            w21s[(c4 + 0) * 17 + token] = v.x;
            w21s[(c4 + 1) * 17 + token] = v.y;
            w21s[(c4 + 2) * 17 + token] = v.z;
            w21s[(c4 + 3) * 17 + token] = v.w;
        }
    }
    __syncwarp();

    // ============ main GEMM, two interleaved j-streams ======================
    float C[8][4];
    #pragma unroll
    for (int nt = 0; nt < 8; nt++)
        #pragma unroll
        for (int k = 0; k < 4; k++) C[nt][k] = 0.f;

    for (int jj = 0; jj < 32; jj++) {
        const int jA = jj, jB = 32 + jj;
        float vA0 = w21s[jA * 17 + g], vA1 = w21s[jA * 17 + g + 8];
        float vB0 = w21s[jB * 17 + g], vB1 = w21s[jB * 17 + g + 8];
        uint32_t hA0 = f16x2(vA0, vA0), hA1 = f16x2(vA1, vA1);
        uint32_t hB0 = f16x2(vB0, vB0), hB1 = f16x2(vB1, vB1);
        const uint8_t* pA = g_BpkH + jA * 8192 + l * 16;
        const uint8_t* pB = g_BpkH + jB * 8192 + l * 16;

        uint4 RA0, RA1, RA2, RA3;
        RA0 = __ldg((const uint4*)(pA +    0));
        RA1 = __ldg((const uint4*)(pA +  512));
        RA2 = __ldg((const uint4*)(pA + 1024));
        RA3 = __ldg((const uint4*)(pA + 1536));

        #pragma unroll
        for (int kc = 0; kc < 4; kc++) {
            uint4 RB0 = __ldg((const uint4*)(pB + (kc * 4 + 0) * 512));
            uint4 RB1 = __ldg((const uint4*)(pB + (kc * 4 + 1) * 512));
            uint4 RB2 = __ldg((const uint4*)(pB + (kc * 4 + 2) * 512));
            uint4 RB3 = __ldg((const uint4*)(pB + (kc * 4 + 3) * 512));
            {
                uint32_t A[4];
                A[0] = hmul2(hA0, w12p[kc*4+0]);
                A[1] = hmul2(hA1, w12p[kc*4+1]);
                A[2] = hmul2(hA0, w12p[kc*4+2]);
                A[3] = hmul2(hA1, w12p[kc*4+3]);
                MMA_F16(C[0], A, RA0.x, RA0.y);
                MMA_F16(C[1], A, RA0.z, RA0.w);
                MMA_F16(C[2], A, RA1.x, RA1.y);
                MMA_F16(C[3], A, RA1.z, RA1.w);
                MMA_F16(C[4], A, RA2.x, RA2.y);
                MMA_F16(C[5], A, RA2.z, RA2.w);
                MMA_F16(C[6], A, RA3.x, RA3.y);
                MMA_F16(C[7], A, RA3.z, RA3.w);
            }
            if (kc < 3) {
                RA0 = __ldg((const uint4*)(pA + ((kc+1) * 4 + 0) * 512));
                RA1 = __ldg((const uint4*)(pA + ((kc+1) * 4 + 1) * 512));
                RA2 = __ldg((const uint4*)(pA + ((kc+1) * 4 + 2) * 512));
                RA3 = __ldg((const uint4*)(pA + ((kc+1) * 4 + 3) * 512));
            }
            {
                uint32_t A[4];
                A[0] = hmul2(hB0, w12p[kc*4+0]);
                A[1] = hmul2(hB1, w12p[kc*4+1]);
                A[2] = hmul2(hB0, w12p[kc*4+2]);
                A[3] = hmul2(hB1, w12p[kc*4+3]);
                MMA_F16(C[0], A, RB0.x, RB0.y);
                MMA_F16(C[1], A, RB0.z, RB0.w);
                MMA_F16(C[2], A, RB1.x, RB1.y);
                MMA_F16(C[3], A, RB1.z, RB1.w);
                MMA_F16(C[4], A, RB2.x, RB2.y);
                MMA_F16(C[5], A, RB2.z, RB2.w);
                MMA_F16(C[6], A, RB3.x, RB3.y);
                MMA_F16(C[7], A, RB3.z, RB3.w);
            }
        }
    }

    // j = 64 bias chunk: A-frags are w12p directly
    {
        const uint8_t* p = g_BpkH + 64 * 8192 + l * 16;
        #pragma unroll
        for (int kc = 0; kc < 4; kc++) {
            uint4 R0 = __ldg((const uint4*)(p + (kc * 4 + 0) * 512));
            uint4 R1 = __ldg((const uint4*)(p + (kc * 4 + 1) * 512));
            uint4 R2 = __ldg((const uint4*)(p + (kc * 4 + 2) * 512));
            uint4 R3 = __ldg((const uint4*)(p + (kc * 4 + 3) * 512));
            uint32_t A[4] = {w12p[kc*4+0], w12p[kc*4+1], w12p[kc*4+2], w12p[kc*4+3]};
            MMA_F16(C[0], A, R0.x, R0.y);
            MMA_F16(C[1], A, R0.z, R0.w);
            MMA_F16(C[2], A, R1.x, R1.y);
            MMA_F16(C[3], A, R1.z, R1.w);
            MMA_F16(C[4], A, R2.x, R2.y);
            MMA_F16(C[5], A, R2.z, R2.w);
            MMA_F16(C[6], A, R3.x, R3.y);
            MMA_F16(C[7], A, R3.z, R3.w);
        }
    }

    // ================= LN + ReLU + y@W3 + b3 ================================
    {
        float sa = 0.f, sb2 = 0.f;
        #pragma unroll
        for (int nt = 0; nt < 8; nt++) { sa += C[nt][0] + C[nt][1]; sb2 += C[nt][2] + C[nt][3]; }
        sa  += __shfl_xor_sync(0xffffffffu, sa, 1);
        sa  += __shfl_xor_sync(0xffffffffu, sa, 2);
        sb2 += __shfl_xor_sync(0xffffffffu, sb2, 1);
        sb2 += __shfl_xor_sync(0xffffffffu, sb2, 2);
        float mua = sa * (1.0f / 64.0f), mub = sb2 * (1.0f / 64.0f);
        float qa = 0.f, qb = 0.f;
        #pragma unroll
        for (int nt = 0; nt < 8; nt++) {
            C[nt][0] -= mua; C[nt][1] -= mua; C[nt][2] -= mub; C[nt][3] -= mub;
            qa = fmaf(C[nt][0], C[nt][0], qa); qa = fmaf(C[nt][1], C[nt][1], qa);
            qb = fmaf(C[nt][2], C[nt][2], qb); qb = fmaf(C[nt][3], C[nt][3], qb);
        }
        qa += __shfl_xor_sync(0xffffffffu, qa, 1);
        qa += __shfl_xor_sync(0xffffffffu, qa, 2);
        qb += __shfl_xor_sync(0xffffffffu, qb, 1);
        qb += __shfl_xor_sync(0xffffffffu, qb, 2);
        float rsa = rsqrtf(qa * (1.0f / 64.0f) + 1e-5f);
        float rsb = rsqrtf(qb * (1.0f / 64.0f) + 1e-5f);
        #pragma unroll
        for (int nt = 0; nt < 8; nt++) {
            int col = nt * 8 + q2;
            float g0 = __ldg(lnG + col), g1 = __ldg(lnG + col + 1);
            float e0 = __ldg(lnB + col), e1 = __ldg(lnB + col + 1);
            C[nt][0] = fmaxf(fmaf(C[nt][0] * rsa, g0, e0), 0.f);
            C[nt][1] = fmaxf(fmaf(C[nt][1] * rsa, g1, e1), 0.f);
            C[nt][2] = fmaxf(fmaf(C[nt][2] * rsb, g0, e0), 0.f);
            C[nt][3] = fmaxf(fmaf(C[nt][3] * rsb, g1, e1), 0.f);
        }
    }
    {
        float D[8][4];
        #pragma unroll
        for (int nt = 0; nt < 8; nt++)
            #pragma unroll
            for (int k = 0; k < 4; k++) D[nt][k] = 0.f;

        #pragma unroll
        for (int kc = 0; kc < 4; kc++) {
            uint32_t A[4];
            A[0] = f16x2(C[2*kc][0],   C[2*kc][1]);
            A[1] = f16x2(C[2*kc][2],   C[2*kc][3]);
            A[2] = f16x2(C[2*kc+1][0], C[2*kc+1][1]);
            A[3] = f16x2(C[2*kc+1][2], C[2*kc+1][3]);
            const uint8_t* panel = g_W3pkH + l * 16;
            uint4 bb0 = __ldg((const uint4*)(panel + (kc * 4 + 0) * 512));
            uint4 bb1 = __ldg((const uint4*)(panel + (kc * 4 + 1) * 512));
            uint4 bb2 = __ldg((const uint4*)(panel + (kc * 4 + 2) * 512));
            uint4 bb3 = __ldg((const uint4*)(panel + (kc * 4 + 3) * 512));
            MMA_F16(D[0], A, bb0.x, bb0.y);
            MMA_F16(D[1], A, bb0.z, bb0.w);
            MMA_F16(D[2], A, bb1.x, bb1.y);
            MMA_F16(D[3], A, bb1.z, bb1.w);
            MMA_F16(D[4], A, bb2.x, bb2.y);
            MMA_F16(D[5], A, bb2.z, bb2.w);
            MMA_F16(D[6], A, bb3.x, bb3.y);
            MMA_F16(D[7], A, bb3.z, bb3.w);
        }

        float* outA = out + gra * 64;
        float* outB = out + grb * 64;
        #pragma unroll
        for (int nt = 0; nt < 8; nt++) {
            int col = nt * 8 + q2;
            float b30 = __ldg(b3 + col), b31 = __ldg(b3 + col + 1);
            *(float2*)(outA + col) = make_float2(D[nt][0] + b30, D[nt][1] + b31);
            *(float2*)(outB + col) = make_float2(D[nt][2] + b30, D[nt][3] + b31);
        }
    }
}

// ---------------------------------------------------------------------------
extern "C" void kernel_launch(void* const* d_in, const int* in_sizes, int n_in,
                              void* d_out, int out_size)
{
    const float* img = (const float*)d_in[0];
    const float* loc = (const float*)d_in[1];
    const float* W11 = (const float*)d_in[2];
    const float* b11 = (const float*)d_in[3];
    const float* W12 = (const float*)d_in[4];
    const float* b12 = (const float*)d_in[5];
    const float* W21 = (const float*)d_in[6];
    const float* b21 = (const float*)d_in[7];
    const float* W22 = (const float*)d_in[8];
    const float* b22 = (const float*)d_in[9];
    const float* lnG = (const float*)d_in[10];
    const float* lnB = (const float*)d_in[11];
    const float* W3  = (const float*)d_in[12];
    const float* b3  = (const float*)d_in[13];
    float* out = (float*)d_out;

    cudaFuncSetAttribute(main_kernel, cudaFuncAttributeMaxDynamicSharedMemorySize, (int)S_SZ);

    convert_kernel<<<152, 256>>>(W22, b22, W3, W11, W21, W12);
    prep_kernel<<<NCTA, 128>>>(img, loc, b11, b21, b12);
    main_kernel<<<NCTA, 128, S_SZ>>>(lnG, lnB, b3, out);
}

// round 15
// speedup vs baseline: 1.1363x; 1.1363x over previous
#include <cuda_runtime.h>
#include <cuda_bf16.h>
#include <cstdint>

#define TOK_TOTAL 32768
#define NCTA 512                  // 64 tokens per CTA, 2 warps x 32 tokens

extern __shared__ __align__(128) uint8_t smbuf[];

// fp16 B panels, v4-packed (layout unchanged from R8/R9)
__device__ __align__(16) uint8_t g_BpkH[65 * 8192];
__device__ __align__(16) uint8_t g_W3pkH[8192];
__device__ __align__(16) uint8_t g_W11pk[32768];
__device__ __align__(16) uint8_t g_W21pk[32768];
__device__ __align__(16) uint8_t g_W12pk[16384];

// ---------------------------------------------------------------------------
__device__ __forceinline__ void split_pair(float v0, float v1, uint32_t& h, uint32_t& l) {
    asm("cvt.rn.bf16x2.f32 %0, %1, %2;" : "=r"(h) : "f"(v1), "f"(v0));
    float h0 = __uint_as_float(h << 16);
    float h1 = __uint_as_float(h & 0xffff0000u);
    asm("cvt.rn.bf16x2.f32 %0, %1, %2;" : "=r"(l) : "f"(v1 - h1), "f"(v0 - h0));
}
__device__ __forceinline__ uint32_t f16x2(float v0, float v1) {
    uint32_t r;
    asm("cvt.rn.f16x2.f32 %0, %1, %2;" : "=r"(r) : "f"(v1), "f"(v0));
    return r;
}
__device__ __forceinline__ uint32_t hmul2(uint32_t a, uint32_t b) {
    uint32_t r;
    asm("mul.rn.f16x2 %0, %1, %2;" : "=r"(r) : "r"(a), "r"(b));
    return r;
}

#define MMA_BF16(Cq, A, b0, b1)                                              \
    asm volatile("mma.sync.aligned.m16n8k16.row.col.f32.bf16.bf16.f32 "      \
                 "{%0,%1,%2,%3}, {%4,%5,%6,%7}, {%8,%9}, {%0,%1,%2,%3};"     \
                 : "+f"((Cq)[0]), "+f"((Cq)[1]), "+f"((Cq)[2]), "+f"((Cq)[3])\
                 : "r"((A)[0]), "r"((A)[1]), "r"((A)[2]), "r"((A)[3]),       \
                   "r"(b0), "r"(b1))

#define MMA_F16(Cq, A, b0, b1)                                               \
    asm volatile("mma.sync.aligned.m16n8k16.row.col.f32.f16.f16.f32 "        \
                 "{%0,%1,%2,%3}, {%4,%5,%6,%7}, {%8,%9}, {%0,%1,%2,%3};"     \
                 : "+f"((Cq)[0]), "+f"((Cq)[1]), "+f"((Cq)[2]), "+f"((Cq)[3])\
                 : "r"((A)[0]), "r"((A)[1]), "r"((A)[2]), "r"((A)[3]),       \
                   "r"(b0), "r"(b1))

// ---------------------------------------------------------------------------
// Convert (unchanged)
// ---------------------------------------------------------------------------
__device__ __forceinline__ void pack_frag_bf(const float* src, uint8_t* dst,
                                             int kc, int nt, int l, int loOff) {
    int q2 = (l & 3) * 2;
    int o  = nt * 8 + (l >> 2);
    int i0 = kc * 16 + q2;
    float v0 = src[(i0    ) * 64 + o];
    float v1 = src[(i0 + 1) * 64 + o];
    float v2 = src[(i0 + 8) * 64 + o];
    float v3 = src[(i0 + 9) * 64 + o];
    uint32_t h0, l0, h1, l1;
    split_pair(v0, v1, h0, l0);
    split_pair(v2, v3, h1, l1);
    uint8_t* d = dst + (kc * 8 + nt) * 256 + l * 8;
    *(uint32_t*)(d)             = h0;
    *(uint32_t*)(d + 4)         = h1;
    *(uint32_t*)(d + loOff)     = l0;
    *(uint32_t*)(d + loOff + 4) = l1;
}
__device__ __forceinline__ void pack_frag_h4(const float* src, uint8_t* dst,
                                             int kc, int np, int l) {
    int q2 = (l & 3) * 2;
    int i0 = kc * 16 + q2;
    uint32_t r[4];
    #pragma unroll
    for (int h = 0; h < 2; h++) {
        int o = (2 * np + h) * 8 + (l >> 2);
        r[h*2+0] = f16x2(src[(i0    ) * 64 + o], src[(i0 + 1) * 64 + o]);
        r[h*2+1] = f16x2(src[(i0 + 8) * 64 + o], src[(i0 + 9) * 64 + o]);
    }
    *(uint4*)(dst + (kc * 4 + np) * 512 + l * 16) = make_uint4(r[0], r[1], r[2], r[3]);
}

__global__ __launch_bounds__(256) void convert_kernel(
    const float* __restrict__ W22, const float* __restrict__ b22,
    const float* __restrict__ W3,  const float* __restrict__ W11,
    const float* __restrict__ W21, const float* __restrict__ W12)
{
    int gid = blockIdx.x * 256 + threadIdx.x;
    if (gid < 33280) {
        int j = gid >> 9;
        int r = gid & 511;
        const float* src = (j < 64) ? (W22 + j * 4096) : b22;
        pack_frag_h4(src, g_BpkH + j * 8192, r >> 7, (r >> 5) & 3, r & 31);
    } else if (gid < 33792) {
        int r = gid - 33280;
        pack_frag_h4(W3, g_W3pkH, r >> 7, (r >> 5) & 3, r & 31);
    } else if (gid < 35840) {
        int r = gid - 33792;
        pack_frag_bf(W11, g_W11pk, r >> 8, (r >> 5) & 7, r & 31, 16384);
    } else if (gid < 37888) {
        int r = gid - 35840;
        pack_frag_bf(W21, g_W21pk, r >> 8, (r >> 5) & 7, r & 31, 16384);
    } else if (gid < 38912) {
        int r = gid - 37888;
        pack_frag_bf(W12, g_W12pk, r >> 8, (r >> 5) & 7, r & 31, 8192);
    }
}

// ---------------------------------------------------------------------------
// Fused kernel: 64 tokens/CTA, 2 warps x 32 tokens (2 m16 tiles each).
// Byte-identical per-warp work to R9; CTA shrunk 128->64 thr so 6 CTAs/SM
// fit -> 12 warps/SM (vs ~7). Entirely barrier-free.
// smem: w21s[64][68] f32 = 17408 B (warp-private columns).
// ---------------------------------------------------------------------------
#define S_SZ 17408u

__device__ __forceinline__ float2 catld(const float* __restrict__ img,
                                        const float* __restrict__ loc,
                                        int row, int c) {
    if (c < 64) return *(const float2*)&img[row * 64 + c];
    return *(const float2*)&loc[row * 64 + c - 64];
}

__global__ __launch_bounds__(64, 6) void fused_kernel(
    const float* __restrict__ img, const float* __restrict__ loc,
    const float* __restrict__ b11, const float* __restrict__ b21,
    const float* __restrict__ b12, const float* __restrict__ lnG,
    const float* __restrict__ lnB, const float* __restrict__ b3,
    float* __restrict__ out)
{
    float* w21s = (float*)smbuf;   // [64][68]

    const int tid = threadIdx.x;
    const int l   = tid & 31;
    const int w   = tid >> 5;      // 0..1
    const int t0  = blockIdx.x * 64;
    const int g   = l >> 2;
    const int q2  = (l & 3) * 2;

    uint32_t w12p[2][16];

    // ===================== Phase 1 (per tile, register-sequenced) ==========
    #pragma unroll
    for (int ti = 0; ti < 2; ti++) {
        const int ra  = w * 32 + ti * 16 + g;
        const int rb  = ra + 8;
        const int gra = t0 + ra, grb = t0 + rb;

        // --- C1 = relu(cat @ W11 + b11), bf16 3-term ---
        float C1[8][4];
        #pragma unroll
        for (int nt = 0; nt < 8; nt++)
            #pragma unroll
            for (int k = 0; k < 4; k++) C1[nt][k] = 0.f;

        #pragma unroll
        for (int kc = 0; kc < 8; kc++) {
            const int i0 = kc * 16 + q2;
            float2 p0 = catld(img, loc, gra, i0);
            float2 p1 = catld(img, loc, grb, i0);
            float2 p2 = catld(img, loc, gra, i0 + 8);
            float2 p3 = catld(img, loc, grb, i0 + 8);
            uint32_t ah[4], al[4];
            split_pair(p0.x, p0.y, ah[0], al[0]);
            split_pair(p1.x, p1.y, ah[1], al[1]);
            split_pair(p2.x, p2.y, ah[2], al[2]);
            split_pair(p3.x, p3.y, ah[3], al[3]);
            #pragma unroll
            for (int nt = 0; nt < 8; nt++) {
                const uint8_t* p = g_W11pk + (kc * 8 + nt) * 256 + l * 8;
                uint2 bh = __ldg((const uint2*)p);
                uint2 bl = __ldg((const uint2*)(p + 16384));
                MMA_BF16(C1[nt], ah, bh.x, bh.y);
                MMA_BF16(C1[nt], ah, bl.x, bl.y);
                MMA_BF16(C1[nt], al, bh.x, bh.y);
            }
        }
        #pragma unroll
        for (int nt = 0; nt < 8; nt++) {
            int col = nt * 8 + q2;
            float u0 = __ldg(b11 + col), u1 = __ldg(b11 + col + 1);
            C1[nt][0] = fmaxf(C1[nt][0] + u0, 0.f);
            C1[nt][1] = fmaxf(C1[nt][1] + u1, 0.f);
            C1[nt][2] = fmaxf(C1[nt][2] + u0, 0.f);
            C1[nt][3] = fmaxf(C1[nt][3] + u1, 0.f);
        }

        // --- W12f = C1 @ W12 + b12 ---
        float Wf[8][4];
        #pragma unroll
        for (int nt = 0; nt < 8; nt++)
            #pragma unroll
            for (int k = 0; k < 4; k++) Wf[nt][k] = 0.f;

        #pragma unroll
        for (int kc = 0; kc < 4; kc++) {
            uint32_t ah[4], al[4];
            split_pair(C1[2*kc][0],   C1[2*kc][1],   ah[0], al[0]);
            split_pair(C1[2*kc][2],   C1[2*kc][3],   ah[1], al[1]);
            split_pair(C1[2*kc+1][0], C1[2*kc+1][1], ah[2], al[2]);
            split_pair(C1[2*kc+1][2], C1[2*kc+1][3], ah[3], al[3]);
            #pragma unroll
            for (int nt = 0; nt < 8; nt++) {
                const uint8_t* p = g_W12pk + (kc * 8 + nt) * 256 + l * 8;
                uint2 bh = __ldg((const uint2*)p);
                uint2 bl = __ldg((const uint2*)(p + 8192));
                MMA_BF16(Wf[nt], ah, bh.x, bh.y);
                MMA_BF16(Wf[nt], ah, bl.x, bl.y);
                MMA_BF16(Wf[nt], al, bh.x, bh.y);
            }
        }
        // bias + pack to f16x2 registers (Wf dies)
        #pragma unroll
        for (int kc = 0; kc < 4; kc++) {
            int c0 = (2*kc) * 8 + q2, c1 = (2*kc+1) * 8 + q2;
            float e00 = __ldg(b12 + c0), e01 = __ldg(b12 + c0 + 1);
            float e10 = __ldg(b12 + c1), e11 = __ldg(b12 + c1 + 1);
            w12p[ti][kc*4+0] = f16x2(Wf[2*kc][0] + e00,   Wf[2*kc][1] + e01);
            w12p[ti][kc*4+1] = f16x2(Wf[2*kc][2] + e00,   Wf[2*kc][3] + e01);
            w12p[ti][kc*4+2] = f16x2(Wf[2*kc+1][0] + e10, Wf[2*kc+1][1] + e11);
            w12p[ti][kc*4+3] = f16x2(Wf[2*kc+1][2] + e10, Wf[2*kc+1][3] + e11);
        }

        // --- C2 = relu(cat @ W21 + b21) -> w21s (reuse C1 regs) ---
        #pragma unroll
        for (int nt = 0; nt < 8; nt++)
            #pragma unroll
            for (int k = 0; k < 4; k++) C1[nt][k] = 0.f;

        #pragma unroll
        for (int kc = 0; kc < 8; kc++) {
            const int i0 = kc * 16 + q2;
            float2 p0 = catld(img, loc, gra, i0);
            float2 p1 = catld(img, loc, grb, i0);
            float2 p2 = catld(img, loc, gra, i0 + 8);
            float2 p3 = catld(img, loc, grb, i0 + 8);
            uint32_t ah[4], al[4];
            split_pair(p0.x, p0.y, ah[0], al[0]);
            split_pair(p1.x, p1.y, ah[1], al[1]);
            split_pair(p2.x, p2.y, ah[2], al[2]);
            split_pair(p3.x, p3.y, ah[3], al[3]);
            #pragma unroll
            for (int nt = 0; nt < 8; nt++) {
                const uint8_t* p = g_W21pk + (kc * 8 + nt) * 256 + l * 8;
                uint2 bh = __ldg((const uint2*)p);
                uint2 bl = __ldg((const uint2*)(p + 16384));
                MMA_BF16(C1[nt], ah, bh.x, bh.y);
                MMA_BF16(C1[nt], ah, bl.x, bl.y);
                MMA_BF16(C1[nt], al, bh.x, bh.y);
            }
        }
        #pragma unroll
        for (int nt = 0; nt < 8; nt++) {
            int col = nt * 8 + q2;
            float v0 = __ldg(b21 + col), v1 = __ldg(b21 + col + 1);
            w21s[(col    ) * 68 + ra] = fmaxf(C1[nt][0] + v0, 0.f);
            w21s[(col + 1) * 68 + ra] = fmaxf(C1[nt][1] + v1, 0.f);
            w21s[(col    ) * 68 + rb] = fmaxf(C1[nt][2] + v0, 0.f);
            w21s[(col + 1) * 68 + rb] = fmaxf(C1[nt][3] + v1, 0.f);
        }
    }
    __syncwarp();   // warp-private smem; only warp-level ordering needed

    // ===================== Phase 2: main bilinear GEMM =====================
    const int ra0 = w * 32 + g, rb0 = ra0 + 8, ra1 = ra0 + 16, rb1 = ra0 + 24;

    float C[2][8][4];
    #pragma unroll
    for (int ti = 0; ti < 2; ti++)
        #pragma unroll
        for (int nt = 0; nt < 8; nt++)
            #pragma unroll
            for (int k = 0; k < 4; k++) C[ti][nt][k] = 0.f;

    for (int j = 0; j < 64; j++) {
        const float* r = w21s + j * 68;
        float v0a = r[ra0], v0b = r[rb0], v1a = r[ra1], v1b = r[rb1];
        uint32_t h0a = f16x2(v0a, v0a), h0b = f16x2(v0b, v0b);
        uint32_t h1a = f16x2(v1a, v1a), h1b = f16x2(v1b, v1b);
        const uint8_t* panel = g_BpkH + j * 8192 + l * 16;

        #pragma unroll
        for (int kc = 0; kc < 4; kc++) {
            uint4 bb0 = __ldg((const uint4*)(panel + (kc * 4 + 0) * 512));
            uint4 bb1 = __ldg((const uint4*)(panel + (kc * 4 + 1) * 512));
            uint4 bb2 = __ldg((const uint4*)(panel + (kc * 4 + 2) * 512));
            uint4 bb3 = __ldg((const uint4*)(panel + (kc * 4 + 3) * 512));
            uint32_t A0[4], A1[4];
            A0[0] = hmul2(h0a, w12p[0][kc*4+0]);
            A0[1] = hmul2(h0b, w12p[0][kc*4+1]);
            A0[2] = hmul2(h0a, w12p[0][kc*4+2]);
            A0[3] = hmul2(h0b, w12p[0][kc*4+3]);
            A1[0] = hmul2(h1a, w12p[1][kc*4+0]);
            A1[1] = hmul2(h1b, w12p[1][kc*4+1]);
            A1[2] = hmul2(h1a, w12p[1][kc*4+2]);
            A1[3] = hmul2(h1b, w12p[1][kc*4+3]);
            MMA_F16(C[0][0], A0, bb0.x, bb0.y);
            MMA_F16(C[0][1], A0, bb0.z, bb0.w);
            MMA_F16(C[0][2], A0, bb1.x, bb1.y);
            MMA_F16(C[0][3], A0, bb1.z, bb1.w);
            MMA_F16(C[0][4], A0, bb2.x, bb2.y);
            MMA_F16(C[0][5], A0, bb2.z, bb2.w);
            MMA_F16(C[0][6], A0, bb3.x, bb3.y);
            MMA_F16(C[0][7], A0, bb3.z, bb3.w);
            MMA_F16(C[1][0], A1, bb0.x, bb0.y);
            MMA_F16(C[1][1], A1, bb0.z, bb0.w);
            MMA_F16(C[1][2], A1, bb1.x, bb1.y);
            MMA_F16(C[1][3], A1, bb1.z, bb1.w);
            MMA_F16(C[1][4], A1, bb2.x, bb2.y);
            MMA_F16(C[1][5], A1, bb2.z, bb2.w);
            MMA_F16(C[1][6], A1, bb3.x, bb3.y);
            MMA_F16(C[1][7], A1, bb3.z, bb3.w);
        }
    }

    // j = 64 bias chunk, peeled: w21 factor = 1 -> A = w12p directly
    {
        const uint8_t* panel = g_BpkH + 64 * 8192 + l * 16;
        #pragma unroll
        for (int kc = 0; kc < 4; kc++) {
            uint4 bb0 = __ldg((const uint4*)(panel + (kc * 4 + 0) * 512));
            uint4 bb1 = __ldg((const uint4*)(panel + (kc * 4 + 1) * 512));
            uint4 bb2 = __ldg((const uint4*)(panel + (kc * 4 + 2) * 512));
            uint4 bb3 = __ldg((const uint4*)(panel + (kc * 4 + 3) * 512));
            #pragma unroll
            for (int ti = 0; ti < 2; ti++) {
                uint32_t A[4] = {w12p[ti][kc*4+0], w12p[ti][kc*4+1],
                                 w12p[ti][kc*4+2], w12p[ti][kc*4+3]};
                MMA_F16(C[ti][0], A, bb0.x, bb0.y);
                MMA_F16(C[ti][1], A, bb0.z, bb0.w);
                MMA_F16(C[ti][2], A, bb1.x, bb1.y);
                MMA_F16(C[ti][3], A, bb1.z, bb1.w);
                MMA_F16(C[ti][4], A, bb2.x, bb2.y);
                MMA_F16(C[ti][5], A, bb2.z, bb2.w);
                MMA_F16(C[ti][6], A, bb3.x, bb3.y);
                MMA_F16(C[ti][7], A, bb3.z, bb3.w);
            }
        }
    }

    // ===================== Phase 3: LN + ReLU + y@W3 + b3 (per tile) =======
    #pragma unroll
    for (int ti = 0; ti < 2; ti++) {
        float (*Ct)[4] = C[ti];
        {
            float sa = 0.f, sb2 = 0.f;
            #pragma unroll
            for (int nt = 0; nt < 8; nt++) { sa += Ct[nt][0] + Ct[nt][1]; sb2 += Ct[nt][2] + Ct[nt][3]; }
            sa  += __shfl_xor_sync(0xffffffffu, sa, 1);
            sa  += __shfl_xor_sync(0xffffffffu, sa, 2);
            sb2 += __shfl_xor_sync(0xffffffffu, sb2, 1);
            sb2 += __shfl_xor_sync(0xffffffffu, sb2, 2);
            float mua = sa * (1.0f / 64.0f), mub = sb2 * (1.0f / 64.0f);
            float qa = 0.f, qb = 0.f;
            #pragma unroll
            for (int nt = 0; nt < 8; nt++) {
                Ct[nt][0] -= mua; Ct[nt][1] -= mua; Ct[nt][2] -= mub; Ct[nt][3] -= mub;
                qa = fmaf(Ct[nt][0], Ct[nt][0], qa); qa = fmaf(Ct[nt][1], Ct[nt][1], qa);
                qb = fmaf(Ct[nt][2], Ct[nt][2], qb); qb = fmaf(Ct[nt][3], Ct[nt][3], qb);
            }
            qa += __shfl_xor_sync(0xffffffffu, qa, 1);
            qa += __shfl_xor_sync(0xffffffffu, qa, 2);
            qb += __shfl_xor_sync(0xffffffffu, qb, 1);
            qb += __shfl_xor_sync(0xffffffffu, qb, 2);
            float rsa = rsqrtf(qa * (1.0f / 64.0f) + 1e-5f);
            float rsb = rsqrtf(qb * (1.0f / 64.0f) + 1e-5f);
            #pragma unroll
            for (int nt = 0; nt < 8; nt++) {
                int col = nt * 8 + q2;
                float g0 = __ldg(lnG + col), g1 = __ldg(lnG + col + 1);
                float e0 = __ldg(lnB + col), e1 = __ldg(lnB + col + 1);
                Ct[nt][0] = fmaxf(fmaf(Ct[nt][0] * rsa, g0, e0), 0.f);
                Ct[nt][1] = fmaxf(fmaf(Ct[nt][1] * rsa, g1, e1), 0.f);
                Ct[nt][2] = fmaxf(fmaf(Ct[nt][2] * rsb, g0, e0), 0.f);
                Ct[nt][3] = fmaxf(fmaf(Ct[nt][3] * rsb, g1, e1), 0.f);
            }
        }
        {
            float D[8][4];
            #pragma unroll
            for (int nt = 0; nt < 8; nt++)
                #pragma unroll
                for (int k = 0; k < 4; k++) D[nt][k] = 0.f;

            #pragma unroll
            for (int kc = 0; kc < 4; kc++) {
                uint32_t A[4];
                A[0] = f16x2(Ct[2*kc][0],   Ct[2*kc][1]);
                A[1] = f16x2(Ct[2*kc][2],   Ct[2*kc][3]);
                A[2] = f16x2(Ct[2*kc+1][0], Ct[2*kc+1][1]);
                A[3] = f16x2(Ct[2*kc+1][2], Ct[2*kc+1][3]);
                const uint8_t* panel = g_W3pkH + l * 16;
                uint4 bb0 = __ldg((const uint4*)(panel + (kc * 4 + 0) * 512));
                uint4 bb1 = __ldg((const uint4*)(panel + (kc * 4 + 1) * 512));
                uint4 bb2 = __ldg((const uint4*)(panel + (kc * 4 + 2) * 512));
                uint4 bb3 = __ldg((const uint4*)(panel + (kc * 4 + 3) * 512));
                MMA_F16(D[0], A, bb0.x, bb0.y);
                MMA_F16(D[1], A, bb0.z, bb0.w);
                MMA_F16(D[2], A, bb1.x, bb1.y);
                MMA_F16(D[3], A, bb1.z, bb1.w);
                MMA_F16(D[4], A, bb2.x, bb2.y);
                MMA_F16(D[5], A, bb2.z, bb2.w);
                MMA_F16(D[6], A, bb3.x, bb3.y);
                MMA_F16(D[7], A, bb3.z, bb3.w);
            }

            const int ra = w * 32 + ti * 16 + g;
            float* outA = out + (t0 + ra) * 64;
            float* outB = out + (t0 + ra + 8) * 64;
            #pragma unroll
            for (int nt = 0; nt < 8; nt++) {
                int col = nt * 8 + q2;
                float b30 = __ldg(b3 + col), b31 = __ldg(b3 + col + 1);
                *(float2*)(outA + col) = make_float2(D[nt][0] + b30, D[nt][1] + b31);
                *(float2*)(outB + col) = make_float2(D[nt][2] + b30, D[nt][3] + b31);
            }
        }
    }
}

// ---------------------------------------------------------------------------
extern "C" void kernel_launch(void* const* d_in, const int* in_sizes, int n_in,
                              void* d_out, int out_size)
{
    const float* img = (const float*)d_in[0];
    const float* loc = (const float*)d_in[1];
    const float* W11 = (const float*)d_in[2];
    const float* b11 = (const float*)d_in[3];
    const float* W12 = (const float*)d_in[4];
    const float* b12 = (const float*)d_in[5];
    const float* W21 = (const float*)d_in[6];
    const float* b21 = (const float*)d_in[7];
    const float* W22 = (const float*)d_in[8];
    const float* b22 = (const float*)d_in[9];
    const float* lnG = (const float*)d_in[10];
    const float* lnB = (const float*)d_in[11];
    const float* W3  = (const float*)d_in[12];
    const float* b3  = (const float*)d_in[13];
    float* out = (float*)d_out;

    cudaFuncSetAttribute(fused_kernel, cudaFuncAttributeMaxDynamicSharedMemorySize, (int)S_SZ);

    convert_kernel<<<152, 256>>>(W22, b22, W3, W11, W21, W12);
    fused_kernel<<<NCTA, 64, S_SZ>>>(img, loc, b11, b21, b12, lnG, lnB, b3, out);
}

// round 16
// speedup vs baseline: 1.3850x; 1.2189x over previous
#include <cuda_runtime.h>
#include <cuda_bf16.h>
#include <cstdint>

#define TOK_TOTAL 32768
#define TILE 128
#define NCTA (TOK_TOTAL / TILE)   // 256 CTAs x 128 thr, 4 warps x 32 tokens

extern __shared__ __align__(128) uint8_t smbuf[];

// fp16 B panels, v4-packed (layout unchanged from R8/R9)
__device__ __align__(16) uint8_t g_BpkH[65 * 8192];
__device__ __align__(16) uint8_t g_W3pkH[8192];
__device__ __align__(16) uint8_t g_W11pk[32768];
__device__ __align__(16) uint8_t g_W21pk[32768];
__device__ __align__(16) uint8_t g_W12pk[16384];

// ---------------------------------------------------------------------------
__device__ __forceinline__ void split_pair(float v0, float v1, uint32_t& h, uint32_t& l) {
    asm("cvt.rn.bf16x2.f32 %0, %1, %2;" : "=r"(h) : "f"(v1), "f"(v0));
    float h0 = __uint_as_float(h << 16);
    float h1 = __uint_as_float(h & 0xffff0000u);
    asm("cvt.rn.bf16x2.f32 %0, %1, %2;" : "=r"(l) : "f"(v1 - h1), "f"(v0 - h0));
}
__device__ __forceinline__ uint32_t f16x2(float v0, float v1) {
    uint32_t r;
    asm("cvt.rn.f16x2.f32 %0, %1, %2;" : "=r"(r) : "f"(v1), "f"(v0));
    return r;
}
__device__ __forceinline__ uint32_t hmul2(uint32_t a, uint32_t b) {
    uint32_t r;
    asm("mul.rn.f16x2 %0, %1, %2;" : "=r"(r) : "r"(a), "r"(b));
    return r;
}

#define MMA_BF16(Cq, A, b0, b1)                                              \
    asm volatile("mma.sync.aligned.m16n8k16.row.col.f32.bf16.bf16.f32 "      \
                 "{%0,%1,%2,%3}, {%4,%5,%6,%7}, {%8,%9}, {%0,%1,%2,%3};"     \
                 : "+f"((Cq)[0]), "+f"((Cq)[1]), "+f"((Cq)[2]), "+f"((Cq)[3])\
                 : "r"((A)[0]), "r"((A)[1]), "r"((A)[2]), "r"((A)[3]),       \
                   "r"(b0), "r"(b1))

#define MMA_F16(Cq, A, b0, b1)                                               \
    asm volatile("mma.sync.aligned.m16n8k16.row.col.f32.f16.f16.f32 "        \
                 "{%0,%1,%2,%3}, {%4,%5,%6,%7}, {%8,%9}, {%0,%1,%2,%3};"     \
                 : "+f"((Cq)[0]), "+f"((Cq)[1]), "+f"((Cq)[2]), "+f"((Cq)[3])\
                 : "r"((A)[0]), "r"((A)[1]), "r"((A)[2]), "r"((A)[3]),       \
                   "r"(b0), "r"(b1))

// ---------------------------------------------------------------------------
// Convert (unchanged)
// ---------------------------------------------------------------------------
__device__ __forceinline__ void pack_frag_bf(const float* src, uint8_t* dst,
                                             int kc, int nt, int l, int loOff) {
    int q2 = (l & 3) * 2;
    int o  = nt * 8 + (l >> 2);
    int i0 = kc * 16 + q2;
    float v0 = src[(i0    ) * 64 + o];
    float v1 = src[(i0 + 1) * 64 + o];
    float v2 = src[(i0 + 8) * 64 + o];
    float v3 = src[(i0 + 9) * 64 + o];
    uint32_t h0, l0, h1, l1;
    split_pair(v0, v1, h0, l0);
    split_pair(v2, v3, h1, l1);
    uint8_t* d = dst + (kc * 8 + nt) * 256 + l * 8;
    *(uint32_t*)(d)             = h0;
    *(uint32_t*)(d + 4)         = h1;
    *(uint32_t*)(d + loOff)     = l0;
    *(uint32_t*)(d + loOff + 4) = l1;
}
__device__ __forceinline__ void pack_frag_h4(const float* src, uint8_t* dst,
                                             int kc, int np, int l) {
    int q2 = (l & 3) * 2;
    int i0 = kc * 16 + q2;
    uint32_t r[4];
    #pragma unroll
    for (int h = 0; h < 2; h++) {
        int o = (2 * np + h) * 8 + (l >> 2);
        r[h*2+0] = f16x2(src[(i0    ) * 64 + o], src[(i0 + 1) * 64 + o]);
        r[h*2+1] = f16x2(src[(i0 + 8) * 64 + o], src[(i0 + 9) * 64 + o]);
    }
    *(uint4*)(dst + (kc * 4 + np) * 512 + l * 16) = make_uint4(r[0], r[1], r[2], r[3]);
}

__global__ __launch_bounds__(256) void convert_kernel(
    const float* __restrict__ W22, const float* __restrict__ b22,
    const float* __restrict__ W3,  const float* __restrict__ W11,
    const float* __restrict__ W21, const float* __restrict__ W12)
{
    int gid = blockIdx.x * 256 + threadIdx.x;
    if (gid < 33280) {
        int j = gid >> 9;
        int r = gid & 511;
        const float* src = (j < 64) ? (W22 + j * 4096) : b22;
        pack_frag_h4(src, g_BpkH + j * 8192, r >> 7, (r >> 5) & 3, r & 31);
    } else if (gid < 33792) {
        int r = gid - 33280;
        pack_frag_h4(W3, g_W3pkH, r >> 7, (r >> 5) & 3, r & 31);
    } else if (gid < 35840) {
        int r = gid - 33792;
        pack_frag_bf(W11, g_W11pk, r >> 8, (r >> 5) & 7, r & 31, 16384);
    } else if (gid < 37888) {
        int r = gid - 35840;
        pack_frag_bf(W21, g_W21pk, r >> 8, (r >> 5) & 7, r & 31, 16384);
    } else if (gid < 38912) {
        int r = gid - 37888;
        pack_frag_bf(W12, g_W12pk, r >> 8, (r >> 5) & 7, r & 31, 8192);
    }
}

// ---------------------------------------------------------------------------
// Fused kernel (R9 structure): 128 tokens/CTA, 4 warps x 32 tokens.
// Changes vs R9: j=64 chunk peeled (A = w12p directly); next-j w21 values
// prefetched before the kc loop's last stage.
// smem: w21s[64][132] f32 = 33792 B.
// ---------------------------------------------------------------------------
#define S_SZ 33792u

__device__ __forceinline__ float2 catld(const float* __restrict__ img,
                                        const float* __restrict__ loc,
                                        int row, int c) {
    if (c < 64) return *(const float2*)&img[row * 64 + c];
    return *(const float2*)&loc[row * 64 + c - 64];
}

__global__ __launch_bounds__(128, 3) void fused_kernel(
    const float* __restrict__ img, const float* __restrict__ loc,
    const float* __restrict__ b11, const float* __restrict__ b21,
    const float* __restrict__ b12, const float* __restrict__ lnG,
    const float* __restrict__ lnB, const float* __restrict__ b3,
    float* __restrict__ out)
{
    float* w21s = (float*)smbuf;   // [64][132]

    const int tid = threadIdx.x;
    const int l   = tid & 31;
    const int w   = tid >> 5;
    const int t0  = blockIdx.x * TILE;
    const int g   = l >> 2;
    const int q2  = (l & 3) * 2;

    uint32_t w12p[2][16];

    // ===================== Phase 1 (per tile, register-sequenced) ==========
    #pragma unroll
    for (int ti = 0; ti < 2; ti++) {
        const int ra  = w * 32 + ti * 16 + g;
        const int rb  = ra + 8;
        const int gra = t0 + ra, grb = t0 + rb;

        float C1[8][4];
        #pragma unroll
        for (int nt = 0; nt < 8; nt++)
            #pragma unroll
            for (int k = 0; k < 4; k++) C1[nt][k] = 0.f;

        #pragma unroll
        for (int kc = 0; kc < 8; kc++) {
            const int i0 = kc * 16 + q2;
            float2 p0 = catld(img, loc, gra, i0);
            float2 p1 = catld(img, loc, grb, i0);
            float2 p2 = catld(img, loc, gra, i0 + 8);
            float2 p3 = catld(img, loc, grb, i0 + 8);
            uint32_t ah[4], al[4];
            split_pair(p0.x, p0.y, ah[0], al[0]);
            split_pair(p1.x, p1.y, ah[1], al[1]);
            split_pair(p2.x, p2.y, ah[2], al[2]);
            split_pair(p3.x, p3.y, ah[3], al[3]);
            #pragma unroll
            for (int nt = 0; nt < 8; nt++) {
                const uint8_t* p = g_W11pk + (kc * 8 + nt) * 256 + l * 8;
                uint2 bh = __ldg((const uint2*)p);
                uint2 bl = __ldg((const uint2*)(p + 16384));
                MMA_BF16(C1[nt], ah, bh.x, bh.y);
                MMA_BF16(C1[nt], ah, bl.x, bl.y);
                MMA_BF16(C1[nt], al, bh.x, bh.y);
            }
        }
        #pragma unroll
        for (int nt = 0; nt < 8; nt++) {
            int col = nt * 8 + q2;
            float u0 = __ldg(b11 + col), u1 = __ldg(b11 + col + 1);
            C1[nt][0] = fmaxf(C1[nt][0] + u0, 0.f);
            C1[nt][1] = fmaxf(C1[nt][1] + u1, 0.f);
            C1[nt][2] = fmaxf(C1[nt][2] + u0, 0.f);
            C1[nt][3] = fmaxf(C1[nt][3] + u1, 0.f);
        }

        float Wf[8][4];
        #pragma unroll
        for (int nt = 0; nt < 8; nt++)
            #pragma unroll
            for (int k = 0; k < 4; k++) Wf[nt][k] = 0.f;

        #pragma unroll
        for (int kc = 0; kc < 4; kc++) {
            uint32_t ah[4], al[4];
            split_pair(C1[2*kc][0],   C1[2*kc][1],   ah[0], al[0]);
            split_pair(C1[2*kc][2],   C1[2*kc][3],   ah[1], al[1]);
            split_pair(C1[2*kc+1][0], C1[2*kc+1][1], ah[2], al[2]);
            split_pair(C1[2*kc+1][2], C1[2*kc+1][3], ah[3], al[3]);
            #pragma unroll
            for (int nt = 0; nt < 8; nt++) {
                const uint8_t* p = g_W12pk + (kc * 8 + nt) * 256 + l * 8;
                uint2 bh = __ldg((const uint2*)p);
                uint2 bl = __ldg((const uint2*)(p + 8192));
                MMA_BF16(Wf[nt], ah, bh.x, bh.y);
                MMA_BF16(Wf[nt], ah, bl.x, bl.y);
                MMA_BF16(Wf[nt], al, bh.x, bh.y);
            }
        }
        #pragma unroll
        for (int kc = 0; kc < 4; kc++) {
            int c0 = (2*kc) * 8 + q2, c1 = (2*kc+1) * 8 + q2;
            float e00 = __ldg(b12 + c0), e01 = __ldg(b12 + c0 + 1);
            float e10 = __ldg(b12 + c1), e11 = __ldg(b12 + c1 + 1);
            w12p[ti][kc*4+0] = f16x2(Wf[2*kc][0] + e00,   Wf[2*kc][1] + e01);
            w12p[ti][kc*4+1] = f16x2(Wf[2*kc][2] + e00,   Wf[2*kc][3] + e01);
            w12p[ti][kc*4+2] = f16x2(Wf[2*kc+1][0] + e10, Wf[2*kc+1][1] + e11);
            w12p[ti][kc*4+3] = f16x2(Wf[2*kc+1][2] + e10, Wf[2*kc+1][3] + e11);
        }

        // --- C2 = relu(cat @ W21 + b21) -> w21s (reuse C1 regs) ---
        #pragma unroll
        for (int nt = 0; nt < 8; nt++)
            #pragma unroll
            for (int k = 0; k < 4; k++) C1[nt][k] = 0.f;

        #pragma unroll
        for (int kc = 0; kc < 8; kc++) {
            const int i0 = kc * 16 + q2;
            float2 p0 = catld(img, loc, gra, i0);
            float2 p1 = catld(img, loc, grb, i0);
            float2 p2 = catld(img, loc, gra, i0 + 8);
            float2 p3 = catld(img, loc, grb, i0 + 8);
            uint32_t ah[4], al[4];
            split_pair(p0.x, p0.y, ah[0], al[0]);
            split_pair(p1.x, p1.y, ah[1], al[1]);
            split_pair(p2.x, p2.y, ah[2], al[2]);
            split_pair(p3.x, p3.y, ah[3], al[3]);
            #pragma unroll
            for (int nt = 0; nt < 8; nt++) {
                const uint8_t* p = g_W21pk + (kc * 8 + nt) * 256 + l * 8;
                uint2 bh = __ldg((const uint2*)p);
                uint2 bl = __ldg((const uint2*)(p + 16384));
                MMA_BF16(C1[nt], ah, bh.x, bh.y);
                MMA_BF16(C1[nt], ah, bl.x, bl.y);
                MMA_BF16(C1[nt], al, bh.x, bh.y);
            }
        }
        #pragma unroll
        for (int nt = 0; nt < 8; nt++) {
            int col = nt * 8 + q2;
            float v0 = __ldg(b21 + col), v1 = __ldg(b21 + col + 1);
            w21s[(col    ) * 132 + ra] = fmaxf(C1[nt][0] + v0, 0.f);
            w21s[(col + 1) * 132 + ra] = fmaxf(C1[nt][1] + v1, 0.f);
            w21s[(col    ) * 132 + rb] = fmaxf(C1[nt][2] + v0, 0.f);
            w21s[(col + 1) * 132 + rb] = fmaxf(C1[nt][3] + v1, 0.f);
        }
    }
    __syncwarp();   // warp-private columns; warp-level ordering suffices

    // ===================== Phase 2: main bilinear GEMM =====================
    const int ra0 = w * 32 + g, rb0 = ra0 + 8, ra1 = ra0 + 16, rb1 = ra0 + 24;

    float C[2][8][4];
    #pragma unroll
    for (int ti = 0; ti < 2; ti++)
        #pragma unroll
        for (int nt = 0; nt < 8; nt++)
            #pragma unroll
            for (int k = 0; k < 4; k++) C[ti][nt][k] = 0.f;

    // prefetched w21 values for current j
    float v0a, v0b, v1a, v1b;
    {
        const float* r = w21s;
        v0a = r[ra0]; v0b = r[rb0]; v1a = r[ra1]; v1b = r[rb1];
    }

    for (int j = 0; j < 64; j++) {
        uint32_t h0a = f16x2(v0a, v0a), h0b = f16x2(v0b, v0b);
        uint32_t h1a = f16x2(v1a, v1a), h1b = f16x2(v1b, v1b);
        const uint8_t* panel = g_BpkH + j * 8192 + l * 16;

        #pragma unroll
        for (int kc = 0; kc < 4; kc++) {
            uint4 bb0 = __ldg((const uint4*)(panel + (kc * 4 + 0) * 512));
            uint4 bb1 = __ldg((const uint4*)(panel + (kc * 4 + 1) * 512));
            uint4 bb2 = __ldg((const uint4*)(panel + (kc * 4 + 2) * 512));
            uint4 bb3 = __ldg((const uint4*)(panel + (kc * 4 + 3) * 512));

            if (kc == 3 && j < 63) {   // hoist next-j w21 reads above last stage
                const float* r = w21s + (j + 1) * 132;
                v0a = r[ra0]; v0b = r[rb0]; v1a = r[ra1]; v1b = r[rb1];
            }

            uint32_t A0[4], A1[4];
            A0[0] = hmul2(h0a, w12p[0][kc*4+0]);
            A0[1] = hmul2(h0b, w12p[0][kc*4+1]);
            A0[2] = hmul2(h0a, w12p[0][kc*4+2]);
            A0[3] = hmul2(h0b, w12p[0][kc*4+3]);
            A1[0] = hmul2(h1a, w12p[1][kc*4+0]);
            A1[1] = hmul2(h1b, w12p[1][kc*4+1]);
            A1[2] = hmul2(h1a, w12p[1][kc*4+2]);
            A1[3] = hmul2(h1b, w12p[1][kc*4+3]);
            MMA_F16(C[0][0], A0, bb0.x, bb0.y);
            MMA_F16(C[0][1], A0, bb0.z, bb0.w);
            MMA_F16(C[0][2], A0, bb1.x, bb1.y);
            MMA_F16(C[0][3], A0, bb1.z, bb1.w);
            MMA_F16(C[0][4], A0, bb2.x, bb2.y);
            MMA_F16(C[0][5], A0, bb2.z, bb2.w);
            MMA_F16(C[0][6], A0, bb3.x, bb3.y);
            MMA_F16(C[0][7], A0, bb3.z, bb3.w);
            MMA_F16(C[1][0], A1, bb0.x, bb0.y);
            MMA_F16(C[1][1], A1, bb0.z, bb0.w);
            MMA_F16(C[1][2], A1, bb1.x, bb1.y);
            MMA_F16(C[1][3], A1, bb1.z, bb1.w);
            MMA_F16(C[1][4], A1, bb2.x, bb2.y);
            MMA_F16(C[1][5], A1, bb2.z, bb2.w);
            MMA_F16(C[1][6], A1, bb3.x, bb3.y);
            MMA_F16(C[1][7], A1, bb3.z, bb3.w);
        }
    }

    // j = 64 bias chunk, peeled: w21 factor = 1 -> A = w12p directly
    {
        const uint8_t* panel = g_BpkH + 64 * 8192 + l * 16;
        #pragma unroll
        for (int kc = 0; kc < 4; kc++) {
            uint4 bb0 = __ldg((const uint4*)(panel + (kc * 4 + 0) * 512));
            uint4 bb1 = __ldg((const uint4*)(panel + (kc * 4 + 1) * 512));
            uint4 bb2 = __ldg((const uint4*)(panel + (kc * 4 + 2) * 512));
            uint4 bb3 = __ldg((const uint4*)(panel + (kc * 4 + 3) * 512));
            #pragma unroll
            for (int ti = 0; ti < 2; ti++) {
                uint32_t A[4] = {w12p[ti][kc*4+0], w12p[ti][kc*4+1],
                                 w12p[ti][kc*4+2], w12p[ti][kc*4+3]};
                MMA_F16(C[ti][0], A, bb0.x, bb0.y);
                MMA_F16(C[ti][1], A, bb0.z, bb0.w);
                MMA_F16(C[ti][2], A, bb1.x, bb1.y);
                MMA_F16(C[ti][3], A, bb1.z, bb1.w);
                MMA_F16(C[ti][4], A, bb2.x, bb2.y);
                MMA_F16(C[ti][5], A, bb2.z, bb2.w);
                MMA_F16(C[ti][6], A, bb3.x, bb3.y);
                MMA_F16(C[ti][7], A, bb3.z, bb3.w);
            }
        }
    }

    // ===================== Phase 3: LN + ReLU + y@W3 + b3 (per tile) =======
    #pragma unroll
    for (int ti = 0; ti < 2; ti++) {
        float (*Ct)[4] = C[ti];
        {
            float sa = 0.f, sb2 = 0.f;
            #pragma unroll
            for (int nt = 0; nt < 8; nt++) { sa += Ct[nt][0] + Ct[nt][1]; sb2 += Ct[nt][2] + Ct[nt][3]; }
            sa  += __shfl_xor_sync(0xffffffffu, sa, 1);
            sa  += __shfl_xor_sync(0xffffffffu, sa, 2);
            sb2 += __shfl_xor_sync(0xffffffffu, sb2, 1);
            sb2 += __shfl_xor_sync(0xffffffffu, sb2, 2);
            float mua = sa * (1.0f / 64.0f), mub = sb2 * (1.0f / 64.0f);
            float qa = 0.f, qb = 0.f;
            #pragma unroll
            for (int nt = 0; nt < 8; nt++) {
                Ct[nt][0] -= mua; Ct[nt][1] -= mua; Ct[nt][2] -= mub; Ct[nt][3] -= mub;
                qa = fmaf(Ct[nt][0], Ct[nt][0], qa); qa = fmaf(Ct[nt][1], Ct[nt][1], qa);
                qb = fmaf(Ct[nt][2], Ct[nt][2], qb); qb = fmaf(Ct[nt][3], Ct[nt][3], qb);
            }
            qa += __shfl_xor_sync(0xffffffffu, qa, 1);
            qa += __shfl_xor_sync(0xffffffffu, qa, 2);
            qb += __shfl_xor_sync(0xffffffffu, qb, 1);
            qb += __shfl_xor_sync(0xffffffffu, qb, 2);
            float rsa = rsqrtf(qa * (1.0f / 64.0f) + 1e-5f);
            float rsb = rsqrtf(qb * (1.0f / 64.0f) + 1e-5f);
            #pragma unroll
            for (int nt = 0; nt < 8; nt++) {
                int col = nt * 8 + q2;
                float g0 = __ldg(lnG + col), g1 = __ldg(lnG + col + 1);
                float e0 = __ldg(lnB + col), e1 = __ldg(lnB + col + 1);
                Ct[nt][0] = fmaxf(fmaf(Ct[nt][0] * rsa, g0, e0), 0.f);
                Ct[nt][1] = fmaxf(fmaf(Ct[nt][1] * rsa, g1, e1), 0.f);
                Ct[nt][2] = fmaxf(fmaf(Ct[nt][2] * rsb, g0, e0), 0.f);
                Ct[nt][3] = fmaxf(fmaf(Ct[nt][3] * rsb, g1, e1), 0.f);
            }
        }
        {
            float D[8][4];
            #pragma unroll
            for (int nt = 0; nt < 8; nt++)
                #pragma unroll
                for (int k = 0; k < 4; k++) D[nt][k] = 0.f;

            #pragma unroll
            for (int kc = 0; kc < 4; kc++) {
                uint32_t A[4];
                A[0] = f16x2(Ct[2*kc][0],   Ct[2*kc][1]);
                A[1] = f16x2(Ct[2*kc][2],   Ct[2*kc][3]);
                A[2] = f16x2(Ct[2*kc+1][0], Ct[2*kc+1][1]);
                A[3] = f16x2(Ct[2*kc+1][2], Ct[2*kc+1][3]);
                const uint8_t* panel = g_W3pkH + l * 16;
                uint4 bb0 = __ldg((const uint4*)(panel + (kc * 4 + 0) * 512));
                uint4 bb1 = __ldg((const uint4*)(panel + (kc * 4 + 1) * 512));
                uint4 bb2 = __ldg((const uint4*)(panel + (kc * 4 + 2) * 512));
                uint4 bb3 = __ldg((const uint4*)(panel + (kc * 4 + 3) * 512));
                MMA_F16(D[0], A, bb0.x, bb0.y);
                MMA_F16(D[1], A, bb0.z, bb0.w);
                MMA_F16(D[2], A, bb1.x, bb1.y);
                MMA_F16(D[3], A, bb1.z, bb1.w);
                MMA_F16(D[4], A, bb2.x, bb2.y);
                MMA_F16(D[5], A, bb2.z, bb2.w);
                MMA_F16(D[6], A, bb3.x, bb3.y);
                MMA_F16(D[7], A, bb3.z, bb3.w);
            }

            const int ra = w * 32 + ti * 16 + g;
            float* outA = out + (t0 + ra) * 64;
            float* outB = out + (t0 + ra + 8) * 64;
            #pragma unroll
            for (int nt = 0; nt < 8; nt++) {
                int col = nt * 8 + q2;
                float b30 = __ldg(b3 + col), b31 = __ldg(b3 + col + 1);
                *(float2*)(outA + col) = make_float2(D[nt][0] + b30, D[nt][1] + b31);
                *(float2*)(outB + col) = make_float2(D[nt][2] + b30, D[nt][3] + b31);
            }
        }
    }
}

// ---------------------------------------------------------------------------
extern "C" void kernel_launch(void* const* d_in, const int* in_sizes, int n_in,
                              void* d_out, int out_size)
{
    const float* img = (const float*)d_in[0];
    const float* loc = (const float*)d_in[1];
    const float* W11 = (const float*)d_in[2];
    const float* b11 = (const float*)d_in[3];
    const float* W12 = (const float*)d_in[4];
    const float* b12 = (const float*)d_in[5];
    const float* W21 = (const float*)d_in[6];
    const float* b21 = (const float*)d_in[7];
    const float* W22 = (const float*)d_in[8];
    const float* b22 = (const float*)d_in[9];
    const float* lnG = (const float*)d_in[10];
    const float* lnB = (const float*)d_in[11];
    const float* W3  = (const float*)d_in[12];
    const float* b3  = (const float*)d_in[13];
    float* out = (float*)d_out;

    cudaFuncSetAttribute(fused_kernel, cudaFuncAttributeMaxDynamicSharedMemorySize, (int)S_SZ);

    convert_kernel<<<152, 256>>>(W22, b22, W3, W11, W21, W12);
    fused_kernel<<<NCTA, 128, S_SZ>>>(img, loc, b11, b21, b12, lnG, lnB, b3, out);
}

// round 17
// speedup vs baseline: 1.7522x; 1.2652x over previous
#include <cuda_runtime.h>
#include <cuda_bf16.h>
#include <cstdint>

#define TOK_TOTAL 32768
#define TILE 128
#define NCTA (TOK_TOTAL / TILE)   // 256

extern __shared__ __align__(128) uint8_t smbuf[];

// fp16 B panels, v4-packed per-lane fragment order:
//   block (kc, np) = 512 B; lane l -> 16 B = {nt=2np: b0,b1; nt=2np+1: b0,b1},
//   b0 = f16x2(k=i0,i0+1), b1 = f16x2(k=i0+8,i0+9), i0 = kc*16+(l%4)*2, o = nt*8+l/4.
__device__ __align__(16) uint8_t g_BpkH[65 * 8192];   // W22 rows + b22
__device__ __align__(16) uint8_t g_W3pkH[8192];       // W3
// bf16 hi/lo packs for phase 1
__device__ __align__(16) uint8_t g_W11pk[32768];      // K=128: [hi 16K|lo 16K]
__device__ __align__(16) uint8_t g_W21pk[32768];      // K=128: [hi 16K|lo 16K]
__device__ __align__(16) uint8_t g_W12pk[16384];      // K=64:  [hi 8K|lo 8K]

// ---------------------------------------------------------------------------
__device__ __forceinline__ void split_pair(float v0, float v1, uint32_t& h, uint32_t& l) {
    asm("cvt.rn.bf16x2.f32 %0, %1, %2;" : "=r"(h) : "f"(v1), "f"(v0));
    float h0 = __uint_as_float(h << 16);
    float h1 = __uint_as_float(h & 0xffff0000u);
    asm("cvt.rn.bf16x2.f32 %0, %1, %2;" : "=r"(l) : "f"(v1 - h1), "f"(v0 - h0));
}
__device__ __forceinline__ uint32_t f16x2(float v0, float v1) {
    uint32_t r;
    asm("cvt.rn.f16x2.f32 %0, %1, %2;" : "=r"(r) : "f"(v1), "f"(v0));
    return r;
}
__device__ __forceinline__ uint32_t hmul2(uint32_t a, uint32_t b) {
    uint32_t r;
    asm("mul.rn.f16x2 %0, %1, %2;" : "=r"(r) : "r"(a), "r"(b));
    return r;
}

#define MMA_BF16(Cq, A, b0, b1)                                              \
    asm volatile("mma.sync.aligned.m16n8k16.row.col.f32.bf16.bf16.f32 "      \
                 "{%0,%1,%2,%3}, {%4,%5,%6,%7}, {%8,%9}, {%0,%1,%2,%3};"     \
                 : "+f"((Cq)[0]), "+f"((Cq)[1]), "+f"((Cq)[2]), "+f"((Cq)[3])\
                 : "r"((A)[0]), "r"((A)[1]), "r"((A)[2]), "r"((A)[3]),       \
                   "r"(b0), "r"(b1))

#define MMA_F16(Cq, A, b0, b1)                                               \
    asm volatile("mma.sync.aligned.m16n8k16.row.col.f32.f16.f16.f32 "        \
                 "{%0,%1,%2,%3}, {%4,%5,%6,%7}, {%8,%9}, {%0,%1,%2,%3};"     \
                 : "+f"((Cq)[0]), "+f"((Cq)[1]), "+f"((Cq)[2]), "+f"((Cq)[3])\
                 : "r"((A)[0]), "r"((A)[1]), "r"((A)[2]), "r"((A)[3]),       \
                   "r"(b0), "r"(b1))

// ---------------------------------------------------------------------------
// Convert: pack static matrices (one-time, ~5us)
// ---------------------------------------------------------------------------
__device__ __forceinline__ void pack_frag_bf(const float* src, uint8_t* dst,
                                             int kc, int nt, int l, int loOff) {
    int q2 = (l & 3) * 2;
    int o  = nt * 8 + (l >> 2);
    int i0 = kc * 16 + q2;
    float v0 = src[(i0    ) * 64 + o];
    float v1 = src[(i0 + 1) * 64 + o];
    float v2 = src[(i0 + 8) * 64 + o];
    float v3 = src[(i0 + 9) * 64 + o];
    uint32_t h0, l0, h1, l1;
    split_pair(v0, v1, h0, l0);
    split_pair(v2, v3, h1, l1);
    uint8_t* d = dst + (kc * 8 + nt) * 256 + l * 8;
    *(uint32_t*)(d)             = h0;
    *(uint32_t*)(d + 4)         = h1;
    *(uint32_t*)(d + loOff)     = l0;
    *(uint32_t*)(d + loOff + 4) = l1;
}
// fp16 v4 pack: one 16-B write covering an nt-pair for this lane
__device__ __forceinline__ void pack_frag_h4(const float* src, uint8_t* dst,
                                             int kc, int np, int l) {
    int q2 = (l & 3) * 2;
    int i0 = kc * 16 + q2;
    uint32_t r[4];
    #pragma unroll
    for (int h = 0; h < 2; h++) {
        int o = (2 * np + h) * 8 + (l >> 2);
        r[h*2+0] = f16x2(src[(i0    ) * 64 + o], src[(i0 + 1) * 64 + o]);
        r[h*2+1] = f16x2(src[(i0 + 8) * 64 + o], src[(i0 + 9) * 64 + o]);
    }
    *(uint4*)(dst + (kc * 4 + np) * 512 + l * 16) = make_uint4(r[0], r[1], r[2], r[3]);
}

__global__ __launch_bounds__(256) void convert_kernel(
    const float* __restrict__ W22, const float* __restrict__ b22,
    const float* __restrict__ W3,  const float* __restrict__ W11,
    const float* __restrict__ W21, const float* __restrict__ W12)
{
    int gid = blockIdx.x * 256 + threadIdx.x;
    if (gid < 33280) {                       // 65 panels x 512
        int j = gid >> 9;
        int r = gid & 511;
        const float* src = (j < 64) ? (W22 + j * 4096) : b22;
        pack_frag_h4(src, g_BpkH + j * 8192, r >> 7, (r >> 5) & 3, r & 31);
    } else if (gid < 33792) {                // W3: 512
        int r = gid - 33280;
        pack_frag_h4(W3, g_W3pkH, r >> 7, (r >> 5) & 3, r & 31);
    } else if (gid < 35840) {                // W11: 2048
        int r = gid - 33792;
        pack_frag_bf(W11, g_W11pk, r >> 8, (r >> 5) & 7, r & 31, 16384);
    } else if (gid < 37888) {                // W21: 2048
        int r = gid - 35840;
        pack_frag_bf(W21, g_W21pk, r >> 8, (r >> 5) & 7, r & 31, 16384);
    } else if (gid < 38912) {                // W12: 1024
        int r = gid - 37888;
        pack_frag_bf(W12, g_W12pk, r >> 8, (r >> 5) & 7, r & 31, 8192);
    }
}

// ---------------------------------------------------------------------------
// Fused kernel: 128 tokens/CTA, 128 threads (4 warps x 32 tokens = 2 m16
// tiles each). Entirely barrier-free; only smem is w21s (warp-private rows).
// ---------------------------------------------------------------------------
#define S_SZ 33792u   // w21s[64][132] f32

__device__ __forceinline__ float2 catld(const float* __restrict__ img,
                                        const float* __restrict__ loc,
                                        int row, int c) {
    // c is compile-time constant per unrolled kc: c<64 -> img, else loc
    if (c < 64) return *(const float2*)&img[row * 64 + c];
    return *(const float2*)&loc[row * 64 + c - 64];
}

__global__ __launch_bounds__(128, 3) void fused_kernel(
    const float* __restrict__ img, const float* __restrict__ loc,
    const float* __restrict__ b11, const float* __restrict__ b21,
    const float* __restrict__ b12, const float* __restrict__ lnG,
    const float* __restrict__ lnB, const float* __restrict__ b3,
    float* __restrict__ out)
{
    float* w21s = (float*)smbuf;   // [64][132]

    const int tid = threadIdx.x;
    const int l   = tid & 31;
    const int w   = tid >> 5;
    const int t0  = blockIdx.x * TILE;
    const int g   = l >> 2;
    const int q2  = (l & 3) * 2;

    uint32_t w12p[2][16];   // [tile][kc*4 + r]

    // ===================== Phase 1 (per tile, register-sequenced) ==========
    #pragma unroll
    for (int ti = 0; ti < 2; ti++) {
        const int ra  = w * 32 + ti * 16 + g;
        const int rb  = ra + 8;
        const int gra = t0 + ra, grb = t0 + rb;

        // --- C1 = relu(cat @ W11 + b11), bf16 3-term ---
        float C1[8][4];
        #pragma unroll
        for (int nt = 0; nt < 8; nt++)
            #pragma unroll
            for (int k = 0; k < 4; k++) C1[nt][k] = 0.f;

        #pragma unroll
        for (int kc = 0; kc < 8; kc++) {
            const int i0 = kc * 16 + q2;
            float2 p0 = catld(img, loc, gra, i0);
            float2 p1 = catld(img, loc, grb, i0);
            float2 p2 = catld(img, loc, gra, i0 + 8);
            float2 p3 = catld(img, loc, grb, i0 + 8);
            uint32_t ah[4], al[4];
            split_pair(p0.x, p0.y, ah[0], al[0]);
            split_pair(p1.x, p1.y, ah[1], al[1]);
            split_pair(p2.x, p2.y, ah[2], al[2]);
            split_pair(p3.x, p3.y, ah[3], al[3]);
            #pragma unroll
            for (int nt = 0; nt < 8; nt++) {
                const uint8_t* p = g_W11pk + (kc * 8 + nt) * 256 + l * 8;
                uint2 bh = __ldg((const uint2*)p);
                uint2 bl = __ldg((const uint2*)(p + 16384));
                MMA_BF16(C1[nt], ah, bh.x, bh.y);
                MMA_BF16(C1[nt], ah, bl.x, bl.y);
                MMA_BF16(C1[nt], al, bh.x, bh.y);
            }
        }
        #pragma unroll
        for (int nt = 0; nt < 8; nt++) {
            int col = nt * 8 + q2;
            float u0 = __ldg(b11 + col), u1 = __ldg(b11 + col + 1);
            C1[nt][0] = fmaxf(C1[nt][0] + u0, 0.f);
            C1[nt][1] = fmaxf(C1[nt][1] + u1, 0.f);
            C1[nt][2] = fmaxf(C1[nt][2] + u0, 0.f);
            C1[nt][3] = fmaxf(C1[nt][3] + u1, 0.f);
        }

        // --- W12f = C1 @ W12 + b12 ---
        float Wf[8][4];
        #pragma unroll
        for (int nt = 0; nt < 8; nt++)
            #pragma unroll
            for (int k = 0; k < 4; k++) Wf[nt][k] = 0.f;

        #pragma unroll
        for (int kc = 0; kc < 4; kc++) {
            uint32_t ah[4], al[4];
            split_pair(C1[2*kc][0],   C1[2*kc][1],   ah[0], al[0]);
            split_pair(C1[2*kc][2],   C1[2*kc][3],   ah[1], al[1]);
            split_pair(C1[2*kc+1][0], C1[2*kc+1][1], ah[2], al[2]);
            split_pair(C1[2*kc+1][2], C1[2*kc+1][3], ah[3], al[3]);
            #pragma unroll
            for (int nt = 0; nt < 8; nt++) {
                const uint8_t* p = g_W12pk + (kc * 8 + nt) * 256 + l * 8;
                uint2 bh = __ldg((const uint2*)p);
                uint2 bl = __ldg((const uint2*)(p + 8192));
                MMA_BF16(Wf[nt], ah, bh.x, bh.y);
                MMA_BF16(Wf[nt], ah, bl.x, bl.y);
                MMA_BF16(Wf[nt], al, bh.x, bh.y);
            }
        }
        // bias + pack to f16x2 registers (Wf dies)
        #pragma unroll
        for (int kc = 0; kc < 4; kc++) {
            int c0 = (2*kc) * 8 + q2, c1 = (2*kc+1) * 8 + q2;
            float e00 = __ldg(b12 + c0), e01 = __ldg(b12 + c0 + 1);
            float e10 = __ldg(b12 + c1), e11 = __ldg(b12 + c1 + 1);
            w12p[ti][kc*4+0] = f16x2(Wf[2*kc][0] + e00,   Wf[2*kc][1] + e01);
            w12p[ti][kc*4+1] = f16x2(Wf[2*kc][2] + e00,   Wf[2*kc][3] + e01);
            w12p[ti][kc*4+2] = f16x2(Wf[2*kc+1][0] + e10, Wf[2*kc+1][1] + e11);
            w12p[ti][kc*4+3] = f16x2(Wf[2*kc+1][2] + e10, Wf[2*kc+1][3] + e11);
        }

        // --- C2 = relu(cat @ W21 + b21) -> w21s (reuse C1 regs) ---
        #pragma unroll
        for (int nt = 0; nt < 8; nt++)
            #pragma unroll
            for (int k = 0; k < 4; k++) C1[nt][k] = 0.f;

        #pragma unroll
        for (int kc = 0; kc < 8; kc++) {
            const int i0 = kc * 16 + q2;
            float2 p0 = catld(img, loc, gra, i0);
            float2 p1 = catld(img, loc, grb, i0);
            float2 p2 = catld(img, loc, gra, i0 + 8);
            float2 p3 = catld(img, loc, grb, i0 + 8);
            uint32_t ah[4], al[4];
            split_pair(p0.x, p0.y, ah[0], al[0]);
            split_pair(p1.x, p1.y, ah[1], al[1]);
            split_pair(p2.x, p2.y, ah[2], al[2]);
            split_pair(p3.x, p3.y, ah[3], al[3]);
            #pragma unroll
            for (int nt = 0; nt < 8; nt++) {
                const uint8_t* p = g_W21pk + (kc * 8 + nt) * 256 + l * 8;
                uint2 bh = __ldg((const uint2*)p);
                uint2 bl = __ldg((const uint2*)(p + 16384));
                MMA_BF16(C1[nt], ah, bh.x, bh.y);
                MMA_BF16(C1[nt], ah, bl.x, bl.y);
                MMA_BF16(C1[nt], al, bh.x, bh.y);
            }
        }
        #pragma unroll
        for (int nt = 0; nt < 8; nt++) {
            int col = nt * 8 + q2;
            float v0 = __ldg(b21 + col), v1 = __ldg(b21 + col + 1);
            w21s[(col    ) * 132 + ra] = fmaxf(C1[nt][0] + v0, 0.f);
            w21s[(col + 1) * 132 + ra] = fmaxf(C1[nt][1] + v1, 0.f);
            w21s[(col    ) * 132 + rb] = fmaxf(C1[nt][2] + v0, 0.f);
            w21s[(col + 1) * 132 + rb] = fmaxf(C1[nt][3] + v1, 0.f);
        }
    }
    // no barrier needed: each warp reads only its own w21s rows

    // ===================== Phase 2: main bilinear GEMM =====================
    const int ra0 = w * 32 + g, rb0 = ra0 + 8, ra1 = ra0 + 16, rb1 = ra0 + 24;

    float C[2][8][4];
    #pragma unroll
    for (int ti = 0; ti < 2; ti++)
        #pragma unroll
        for (int nt = 0; nt < 8; nt++)
            #pragma unroll
            for (int k = 0; k < 4; k++) C[ti][nt][k] = 0.f;

    for (int j = 0; j <= 64; j++) {
        float v0a = 1.f, v0b = 1.f, v1a = 1.f, v1b = 1.f;
        if (j < 64) {
            const float* r = w21s + j * 132;
            v0a = r[ra0]; v0b = r[rb0]; v1a = r[ra1]; v1b = r[rb1];
        }
        uint32_t h0a = f16x2(v0a, v0a), h0b = f16x2(v0b, v0b);
        uint32_t h1a = f16x2(v1a, v1a), h1b = f16x2(v1b, v1b);
        const uint8_t* panel = g_BpkH + j * 8192 + l * 16;

        #pragma unroll
        for (int kc = 0; kc < 4; kc++) {
            uint4 bb0 = __ldg((const uint4*)(panel + (kc * 4 + 0) * 512));
            uint4 bb1 = __ldg((const uint4*)(panel + (kc * 4 + 1) * 512));
            uint4 bb2 = __ldg((const uint4*)(panel + (kc * 4 + 2) * 512));
            uint4 bb3 = __ldg((const uint4*)(panel + (kc * 4 + 3) * 512));
            uint32_t A0[4], A1[4];
            A0[0] = hmul2(h0a, w12p[0][kc*4+0]);
            A0[1] = hmul2(h0b, w12p[0][kc*4+1]);
            A0[2] = hmul2(h0a, w12p[0][kc*4+2]);
            A0[3] = hmul2(h0b, w12p[0][kc*4+3]);
            A1[0] = hmul2(h1a, w12p[1][kc*4+0]);
            A1[1] = hmul2(h1b, w12p[1][kc*4+1]);
            A1[2] = hmul2(h1a, w12p[1][kc*4+2]);
            A1[3] = hmul2(h1b, w12p[1][kc*4+3]);
            MMA_F16(C[0][0], A0, bb0.x, bb0.y);
            MMA_F16(C[0][1], A0, bb0.z, bb0.w);
            MMA_F16(C[0][2], A0, bb1.x, bb1.y);
            MMA_F16(C[0][3], A0, bb1.z, bb1.w);
            MMA_F16(C[0][4], A0, bb2.x, bb2.y);
            MMA_F16(C[0][5], A0, bb2.z, bb2.w);
            MMA_F16(C[0][6], A0, bb3.x, bb3.y);
            MMA_F16(C[0][7], A0, bb3.z, bb3.w);
            MMA_F16(C[1][0], A1, bb0.x, bb0.y);
            MMA_F16(C[1][1], A1, bb0.z, bb0.w);
            MMA_F16(C[1][2], A1, bb1.x, bb1.y);
            MMA_F16(C[1][3], A1, bb1.z, bb1.w);
            MMA_F16(C[1][4], A1, bb2.x, bb2.y);
            MMA_F16(C[1][5], A1, bb2.z, bb2.w);
            MMA_F16(C[1][6], A1, bb3.x, bb3.y);
            MMA_F16(C[1][7], A1, bb3.z, bb3.w);
        }
    }

    // ===================== Phase 3: LN + ReLU + y@W3 + b3 (per tile) =======
    #pragma unroll
    for (int ti = 0; ti < 2; ti++) {
        float (*Ct)[4] = C[ti];
        {
            float sa = 0.f, sb2 = 0.f;
            #pragma unroll
            for (int nt = 0; nt < 8; nt++) { sa += Ct[nt][0] + Ct[nt][1]; sb2 += Ct[nt][2] + Ct[nt][3]; }
            sa  += __shfl_xor_sync(0xffffffffu, sa, 1);
            sa  += __shfl_xor_sync(0xffffffffu, sa, 2);
            sb2 += __shfl_xor_sync(0xffffffffu, sb2, 1);
            sb2 += __shfl_xor_sync(0xffffffffu, sb2, 2);
            float mua = sa * (1.0f / 64.0f), mub = sb2 * (1.0f / 64.0f);
            float qa = 0.f, qb = 0.f;
            #pragma unroll
            for (int nt = 0; nt < 8; nt++) {
                Ct[nt][0] -= mua; Ct[nt][1] -= mua; Ct[nt][2] -= mub; Ct[nt][3] -= mub;
                qa = fmaf(Ct[nt][0], Ct[nt][0], qa); qa = fmaf(Ct[nt][1], Ct[nt][1], qa);
                qb = fmaf(Ct[nt][2], Ct[nt][2], qb); qb = fmaf(Ct[nt][3], Ct[nt][3], qb);
            }
            qa += __shfl_xor_sync(0xffffffffu, qa, 1);
            qa += __shfl_xor_sync(0xffffffffu, qa, 2);
            qb += __shfl_xor_sync(0xffffffffu, qb, 1);
            qb += __shfl_xor_sync(0xffffffffu, qb, 2);
            float rsa = rsqrtf(qa * (1.0f / 64.0f) + 1e-5f);
            float rsb = rsqrtf(qb * (1.0f / 64.0f) + 1e-5f);
            #pragma unroll
            for (int nt = 0; nt < 8; nt++) {
                int col = nt * 8 + q2;
                float g0 = __ldg(lnG + col), g1 = __ldg(lnG + col + 1);
                float e0 = __ldg(lnB + col), e1 = __ldg(lnB + col + 1);
                Ct[nt][0] = fmaxf(fmaf(Ct[nt][0] * rsa, g0, e0), 0.f);
                Ct[nt][1] = fmaxf(fmaf(Ct[nt][1] * rsa, g1, e1), 0.f);
                Ct[nt][2] = fmaxf(fmaf(Ct[nt][2] * rsb, g0, e0), 0.f);
                Ct[nt][3] = fmaxf(fmaf(Ct[nt][3] * rsb, g1, e1), 0.f);
            }
        }
        {
            float D[8][4];
            #pragma unroll
            for (int nt = 0; nt < 8; nt++)
                #pragma unroll
                for (int k = 0; k < 4; k++) D[nt][k] = 0.f;

            #pragma unroll
            for (int kc = 0; kc < 4; kc++) {
                uint32_t A[4];
                A[0] = f16x2(Ct[2*kc][0],   Ct[2*kc][1]);
                A[1] = f16x2(Ct[2*kc][2],   Ct[2*kc][3]);
                A[2] = f16x2(Ct[2*kc+1][0], Ct[2*kc+1][1]);
                A[3] = f16x2(Ct[2*kc+1][2], Ct[2*kc+1][3]);
                const uint8_t* panel = g_W3pkH + l * 16;
                uint4 bb0 = __ldg((const uint4*)(panel + (kc * 4 + 0) * 512));
                uint4 bb1 = __ldg((const uint4*)(panel + (kc * 4 + 1) * 512));
                uint4 bb2 = __ldg((const uint4*)(panel + (kc * 4 + 2) * 512));
                uint4 bb3 = __ldg((const uint4*)(panel + (kc * 4 + 3) * 512));
                MMA_F16(D[0], A, bb0.x, bb0.y);
                MMA_F16(D[1], A, bb0.z, bb0.w);
                MMA_F16(D[2], A, bb1.x, bb1.y);
                MMA_F16(D[3], A, bb1.z, bb1.w);
                MMA_F16(D[4], A, bb2.x, bb2.y);
                MMA_F16(D[5], A, bb2.z, bb2.w);
                MMA_F16(D[6], A, bb3.x, bb3.y);
                MMA_F16(D[7], A, bb3.z, bb3.w);
            }

            const int ra = w * 32 + ti * 16 + g;
            float* outA = out + (t0 + ra) * 64;
            float* outB = out + (t0 + ra + 8) * 64;
            #pragma unroll
            for (int nt = 0; nt < 8; nt++) {
                int col = nt * 8 + q2;
                float b30 = __ldg(b3 + col), b31 = __ldg(b3 + col + 1);
                *(float2*)(outA + col) = make_float2(D[nt][0] + b30, D[nt][1] + b31);
                *(float2*)(outB + col) = make_float2(D[nt][2] + b30, D[nt][3] + b31);
            }
        }
    }
}

// ---------------------------------------------------------------------------
extern "C" void kernel_launch(void* const* d_in, const int* in_sizes, int n_in,
                              void* d_out, int out_size)
{
    const float* img = (const float*)d_in[0];
    const float* loc = (const float*)d_in[1];
    const float* W11 = (const float*)d_in[2];
    const float* b11 = (const float*)d_in[3];
    const float* W12 = (const float*)d_in[4];
    const float* b12 = (const float*)d_in[5];
    const float* W21 = (const float*)d_in[6];
    const float* b21 = (const float*)d_in[7];
    const float* W22 = (const float*)d_in[8];
    const float* b22 = (const float*)d_in[9];
    const float* lnG = (const float*)d_in[10];
    const float* lnB = (const float*)d_in[11];
    const float* W3  = (const float*)d_in[12];
    const float* b3  = (const float*)d_in[13];
    float* out = (float*)d_out;

    cudaFuncSetAttribute(fused_kernel, cudaFuncAttributeMaxDynamicSharedMemorySize, (int)S_SZ);

    convert_kernel<<<152, 256>>>(W22, b22, W3, W11, W21, W12);
    fused_kernel<<<NCTA, 128, S_SZ>>>(img, loc, b11, b21, b12, lnG, lnB, b3, out);
}